// round 4
// baseline (speedup 1.0000x reference)
#include <cuda_runtime.h>
#include <cuda_bf16.h>

#define D        32     // feature dim (fixed by problem shape)
#define SEG_PER_BLK 32  // segments per 256-thread block (8-lane group per segment)

// ---------------------------------------------------------------------------
// Single kernel: per-segment gather + mean, owner-computes, no atomics.
//
// Block b owns segments [b*32, b*32+32). Boundaries in the sorted sid array
// are found with lower_bound: threads 0 and 32 search the full [0,E) range,
// then threads 1..31 search only within that window (~11 steps). Each 8-lane
// group then owns one segment; lane 'sub' owns feature columns [sub*4,
// sub*4+4) as a float4. Row reads are one coalesced 128B wavefront per edge.
// Result (sum/max(cnt,1)) is written with a single non-atomic STG.128/lane.
// ---------------------------------------------------------------------------
__global__ void __launch_bounds__(256)
k_seg(const float*  __restrict__ src,
      const int*    __restrict__ gidx,
      const int*    __restrict__ sid,
      float4*       __restrict__ out4,
      int E, int N)
{
    __shared__ int bounds[SEG_PER_BLK + 1];

    const int tid      = threadIdx.x;
    const int seg_base = blockIdx.x * SEG_PER_BLK;

    // ---- phase 1: wide searches for the block window ----
    if (tid == 0 || tid == SEG_PER_BLK) {
        int target = seg_base + tid;
        if (target > N) target = N;
        int lo = 0, hi = E;
        while (lo < hi) {
            int mid = (lo + hi) >> 1;
            if (__ldg(sid + mid) < target) lo = mid + 1; else hi = mid;
        }
        bounds[tid] = lo;
    }
    __syncthreads();

    // ---- phase 2: narrow searches inside the window ----
    if (tid >= 1 && tid < SEG_PER_BLK) {
        int target = seg_base + tid;
        if (target > N) target = N;
        int lo = bounds[0], hi = bounds[SEG_PER_BLK];
        while (lo < hi) {
            int mid = (lo + hi) >> 1;
            if (__ldg(sid + mid) < target) lo = mid + 1; else hi = mid;
        }
        bounds[tid] = lo;
    }
    __syncthreads();

    // ---- phase 3: accumulate this group's segment ----
    const int group = tid >> 3;          // 0..31: segment within block
    const int sub   = tid & 7;           // float4 column slot
    const int seg   = seg_base + group;
    if (seg >= N) return;

    const int start = bounds[group];
    const int end   = bounds[group + 1];
    const int cnt   = end - start;

    float4 sum = make_float4(0.f, 0.f, 0.f, 0.f);

    int e = start;
    // batches of 8 edges: 8 independent idx loads, then 8 independent
    // LDG.128 row reads -> MLP = 8 per lane (x4 groups per warp)
    for (; e + 8 <= end; e += 8) {
        int idx[8];
        #pragma unroll
        for (int j = 0; j < 8; ++j) idx[j] = __ldg(gidx + e + j);
        float4 v[8];
        #pragma unroll
        for (int j = 0; j < 8; ++j)
            v[j] = __ldg((const float4*)(src + (long long)idx[j] * D) + sub);
        #pragma unroll
        for (int j = 0; j < 8; ++j) {
            sum.x += v[j].x; sum.y += v[j].y;
            sum.z += v[j].z; sum.w += v[j].w;
        }
    }
    // remainder
    for (; e < end; ++e) {
        int idx = __ldg(gidx + e);
        float4 v = __ldg((const float4*)(src + (long long)idx * D) + sub);
        sum.x += v.x; sum.y += v.y; sum.z += v.z; sum.w += v.w;
    }

    const float inv = 1.0f / fmaxf((float)cnt, 1.0f);
    sum.x *= inv; sum.y *= inv; sum.z *= inv; sum.w *= inv;
    out4[(long long)seg * 8 + sub] = sum;
}

// ---------------------------------------------------------------------------
extern "C" void kernel_launch(void* const* d_in, const int* in_sizes, int n_in,
                              void* d_out, int out_size)
{
    const float* src  = (const float*)d_in[0];   // [N, 32] f32
    const int*   gidx = (const int*)  d_in[1];   // [E] i32
    const int*   sid  = (const int*)  d_in[2];   // [E] i32 (sorted)
    float4*      out4 = (float4*)d_out;          // [N, 32] f32

    const int E = in_sizes[1];
    const int N = out_size / D;

    int blocks = (N + SEG_PER_BLK - 1) / SEG_PER_BLK;
    k_seg<<<blocks, 256>>>(src, gidx, sid, out4, E, N);
}

// round 5
// speedup vs baseline: 1.0997x; 1.0997x over previous
#include <cuda_runtime.h>
#include <cuda_bf16.h>

#define D    32                 // feature dim
#define GC   128                // edges per group (run-length chunk)
#define GPB  32                 // groups per 256-thread block
#define BLOCK_EDGES (GC * GPB)  // 4096 edges per block
#define MAXG (1 << 17)          // max groups supported (E up to 16.7M)

// Per-group partial slots (first run = L, last run = R). Written fresh and
// completely by every k_agg call -> deterministic across graph replays,
// no zero-init or reset ever needed.
__device__ float4 g_Lsum[MAXG * 8];
__device__ float4 g_Rsum[MAXG * 8];
__device__ int    g_Lseg[MAXG];
__device__ int    g_Rseg[MAXG];
__device__ int    g_Lcnt[MAXG];
__device__ int    g_Rcnt[MAXG];

// smem skew: group lgrp's data at stride GC+4 -> conflict-free group reads
__device__ __forceinline__ int skew(int i) { return i + (i >> 7) * 4; }

__device__ __forceinline__ float4 f4zero() { return make_float4(0.f, 0.f, 0.f, 0.f); }

// ---------------------------------------------------------------------------
// Kernel 1: gather + segment aggregation.
// Block stages 4096 edge indices in smem; each 8-lane group run-length
// accumulates 128 contiguous edges in uniform batches of 8 (MLP=8/lane).
// Interior runs are complete segments -> direct non-atomic mean store.
// First/last runs -> per-group partial slots. In-chunk gaps -> zero rows.
// ---------------------------------------------------------------------------
__global__ void __launch_bounds__(256)
k_agg(const float* __restrict__ src,
      const int*   __restrict__ gidx,
      const int*   __restrict__ sid,
      float4*      __restrict__ out4,
      int E, int ngroups)
{
    __shared__ int s_gi[GPB * (GC + 4)];
    __shared__ int s_si[GPB * (GC + 4)];

    const int tid = threadIdx.x;
    const long long bbase = (long long)blockIdx.x * BLOCK_EDGES;
    const int nedges = (int)min((long long)BLOCK_EDGES, (long long)E - bbase);

    // ---- stage indices (int4 coalesced + scalar tail) ----
    {
        const int nv = nedges >> 2;
        const int4* gp = (const int4*)(gidx + bbase);
        const int4* sp = (const int4*)(sid  + bbase);
        for (int i = tid; i < nv; i += 256) {
            int4 a = __ldg(gp + i);
            int4 b = __ldg(sp + i);
            int o = skew(i * 4);           // 4 consecutive stay in one group
            s_gi[o] = a.x; s_gi[o+1] = a.y; s_gi[o+2] = a.z; s_gi[o+3] = a.w;
            s_si[o] = b.x; s_si[o+1] = b.y; s_si[o+2] = b.z; s_si[o+3] = b.w;
        }
        for (int i = (nv << 2) + tid; i < nedges; i += 256) {
            int o = skew(i);
            s_gi[o] = __ldg(gidx + bbase + i);
            s_si[o] = __ldg(sid  + bbase + i);
        }
    }
    __syncthreads();

    const int lgrp = tid >> 3;                 // group within block
    const int sub  = tid & 7;                  // float4 column slot
    const int g    = blockIdx.x * GPB + lgrp;  // global group id
    if (g >= ngroups) return;
    const int goff = lgrp * GC;
    const int lim  = min(GC, nedges - goff);   // >0 since g < ngroups

    int    cur = -1, cnt = 0;
    bool   first_done = false;
    float4 sum = f4zero();

    int e = 0;
    const int nb = lim >> 3;
    for (int b = 0; b < nb; ++b, e += 8) {
        int idx[8], sg[8];
        #pragma unroll
        for (int j = 0; j < 8; ++j) {
            int o = skew(goff + e + j);
            idx[j] = s_gi[o];
            sg[j]  = s_si[o];
        }
        float4 v[8];
        #pragma unroll
        for (int j = 0; j < 8; ++j)
            v[j] = __ldg((const float4*)(src + (long long)idx[j] * D) + sub);
        #pragma unroll
        for (int j = 0; j < 8; ++j) {
            if (sg[j] != cur) {
                if (cnt) {
                    if (!first_done) {         // first run -> L slot
                        g_Lsum[g * 8 + sub] = sum;
                        if (sub == 0) { g_Lseg[g] = cur; g_Lcnt[g] = cnt; }
                        first_done = true;
                    } else {                   // interior run: complete segment
                        float inv = 1.0f / (float)cnt;
                        float4 m = make_float4(sum.x*inv, sum.y*inv, sum.z*inv, sum.w*inv);
                        out4[(long long)cur * 8 + sub] = m;
                    }
                }
                if (cur >= 0)                  // in-chunk empty segments
                    for (int s = cur + 1; s < sg[j]; ++s)
                        out4[(long long)s * 8 + sub] = f4zero();
                cur = sg[j]; sum = f4zero(); cnt = 0;
            }
            sum.x += v[j].x; sum.y += v[j].y; sum.z += v[j].z; sum.w += v[j].w;
            ++cnt;
        }
    }
    // scalar remainder (only last group of last block)
    for (; e < lim; ++e) {
        int o = skew(goff + e);
        int idx = s_gi[o], sg = s_si[o];
        float4 v = __ldg((const float4*)(src + (long long)idx * D) + sub);
        if (sg != cur) {
            if (cnt) {
                if (!first_done) {
                    g_Lsum[g * 8 + sub] = sum;
                    if (sub == 0) { g_Lseg[g] = cur; g_Lcnt[g] = cnt; }
                    first_done = true;
                } else {
                    float inv = 1.0f / (float)cnt;
                    out4[(long long)cur * 8 + sub] =
                        make_float4(sum.x*inv, sum.y*inv, sum.z*inv, sum.w*inv);
                }
            }
            if (cur >= 0)
                for (int s = cur + 1; s < sg; ++s)
                    out4[(long long)s * 8 + sub] = f4zero();
            cur = sg; sum = f4zero(); cnt = 0;
        }
        sum.x += v.x; sum.y += v.y; sum.z += v.z; sum.w += v.w;
        ++cnt;
    }

    // final flush: last run -> R slot (or L if it is also the first run)
    if (!first_done) {
        g_Lsum[g * 8 + sub] = sum;
        g_Rsum[g * 8 + sub] = f4zero();
        if (sub == 0) { g_Lseg[g] = cur; g_Lcnt[g] = cnt;
                        g_Rseg[g] = -1;  g_Rcnt[g] = 0; }
    } else {
        g_Rsum[g * 8 + sub] = sum;
        if (sub == 0) { g_Rseg[g] = cur; g_Rcnt[g] = cnt; }
    }
}

// ---------------------------------------------------------------------------
// Kernel 2: stitch boundary segments from partial slots + fill empties.
// 8 threads per group. Duplicate owners compute identical totals -> idempotent.
// ---------------------------------------------------------------------------
__global__ void __launch_bounds__(256)
k_fin(float4* __restrict__ out4, int ngroups, int N)
{
    const int t = blockIdx.x * blockDim.x + threadIdx.x;
    const int g = t >> 3, sub = t & 7;
    if (g >= ngroups) return;

    const int sL = g_Lseg[g];
    float4 tot = g_Lsum[g * 8 + sub];
    float  tc  = (float)g_Lcnt[g];

    // scan left: add contributions from previous groups ending in sL
    for (int b = g - 1; b >= 0; --b) {
        int rs = g_Rseg[b];
        if (rs == sL) {                         // sL is b's last run; starts in b or earlier
            tot.x += g_Rsum[b*8+sub].x; tot.y += g_Rsum[b*8+sub].y;
            tot.z += g_Rsum[b*8+sub].z; tot.w += g_Rsum[b*8+sub].w;
            tc += (float)g_Rcnt[b];
            break;                              // R valid => L(b) != sL => sL starts in b
        }
        if (rs == -1 && g_Lseg[b] == sL) {      // b entirely inside sL
            tot.x += g_Lsum[b*8+sub].x; tot.y += g_Lsum[b*8+sub].y;
            tot.z += g_Lsum[b*8+sub].z; tot.w += g_Lsum[b*8+sub].w;
            tc += (float)g_Lcnt[b];
            continue;
        }
        break;
    }
    // scan right: only possible if this group is single-run
    if (g_Rseg[g] == -1) {
        for (int b = g + 1; b < ngroups; ++b) {
            if (g_Lseg[b] != sL) break;
            tot.x += g_Lsum[b*8+sub].x; tot.y += g_Lsum[b*8+sub].y;
            tot.z += g_Lsum[b*8+sub].z; tot.w += g_Lsum[b*8+sub].w;
            tc += (float)g_Lcnt[b];
            if (g_Rseg[b] != -1) break;         // sL ends inside b
        }
    }
    {
        float inv = 1.0f / fmaxf(tc, 1.0f);
        out4[(long long)sL * 8 + sub] =
            make_float4(tot.x*inv, tot.y*inv, tot.z*inv, tot.w*inv);
    }

    // last run of this group, if confined to it
    const int sR    = g_Rseg[g];
    const int nextL = (g + 1 < ngroups) ? g_Lseg[g + 1] : N;
    if (sR != -1 && sR != nextL) {
        float4 r = g_Rsum[g * 8 + sub];
        float inv = 1.0f / fmaxf((float)g_Rcnt[g], 1.0f);
        out4[(long long)sR * 8 + sub] = make_float4(r.x*inv, r.y*inv, r.z*inv, r.w*inv);
    }

    // empty segments between this chunk's last segment and the next chunk's first
    const int lastseg = (sR == -1) ? sL : sR;
    for (int s = lastseg + 1; s < nextL; ++s)
        out4[(long long)s * 8 + sub] = f4zero();
    if (g == 0)
        for (int s = 0; s < sL; ++s)
            out4[(long long)s * 8 + sub] = f4zero();
}

// ---------------------------------------------------------------------------
extern "C" void kernel_launch(void* const* d_in, const int* in_sizes, int n_in,
                              void* d_out, int out_size)
{
    const float* src  = (const float*)d_in[0];   // [N, 32] f32
    const int*   gidx = (const int*)  d_in[1];   // [E] i32
    const int*   sid  = (const int*)  d_in[2];   // [E] i32 (sorted)
    float4*      out4 = (float4*)d_out;          // [N, 32] f32

    const int E = in_sizes[1];
    const int N = out_size / D;
    const int ngroups = (E + GC - 1) / GC;

    // 1) aggregate (direct stores for interior segments, slots for boundaries)
    {
        int blocks = (ngroups + GPB - 1) / GPB;
        k_agg<<<blocks, 256>>>(src, gidx, sid, out4, E, ngroups);
    }
    // 2) stitch boundaries + empties
    {
        int threads = ngroups * 8;
        int blocks  = (threads + 255) / 256;
        k_fin<<<blocks, 256>>>(out4, ngroups, N);
    }
}

// round 6
// speedup vs baseline: 1.1674x; 1.0615x over previous
#include <cuda_runtime.h>
#include <cuda_bf16.h>

#define FULL_MASK 0xffffffffu
#define EPW 128          // edges per warp-chunk (4 groups x 32 edges)
#define D   32           // feature dim (fixed by problem shape)
#define SPB 256          // segments per k_pre block

// Per-segment 1/max(count,1). Fully rewritten for all n<N on every call ->
// deterministic across graph replays; no allocation, no reset needed.
__device__ float g_inv[1 << 20];   // 4 MB, supports N up to 1M

// ---------------------------------------------------------------------------
// Kernel 1: counts via binary search on sorted sid + zero-init output rows.
// Block owns segments [b*256, b*256+256). Threads 0/255 do full-range
// lower_bound searches to bound the window; remaining threads do narrow
// searches inside it (window ~E/N*256 entries, L1-resident).
// ---------------------------------------------------------------------------
__global__ void __launch_bounds__(SPB)
k_pre(const int* __restrict__ sid,
      float4*    __restrict__ out4,
      int E, int N)
{
    __shared__ int bnd[SPB + 1];

    const int tid      = threadIdx.x;
    const int seg_base = blockIdx.x * SPB;

    // wide searches for window ends (sid values are < N, so lower_bound of
    // any target >= N returns E — no clamping needed)
    if (tid == 0 || tid == 1) {
        int target = seg_base + tid * SPB;
        int lo = 0, hi = E;
        while (lo < hi) {
            int mid = (lo + hi) >> 1;
            if (__ldg(sid + mid) < target) lo = mid + 1; else hi = mid;
        }
        bnd[tid * SPB] = lo;
    }
    __syncthreads();

    // narrow searches inside the window
    if (tid >= 1 && tid < SPB) {
        int target = seg_base + tid;
        int lo = bnd[0], hi = bnd[SPB];
        while (lo < hi) {
            int mid = (lo + hi) >> 1;
            if (__ldg(sid + mid) < target) lo = mid + 1; else hi = mid;
        }
        bnd[tid] = lo;
    }
    __syncthreads();

    const int seg = seg_base + tid;
    if (seg < N) {
        int cnt = bnd[tid + 1] - bnd[tid];
        g_inv[seg] = 1.0f / (float)max(cnt, 1);
    }

    // zero this block's 256 output rows (2048 quads), coalesced
    const long long qbase = (long long)seg_base * 8;
    const long long qend  = min(qbase + SPB * 8, (long long)N * 8);
    for (long long q = qbase + tid; q < qend; q += SPB)
        out4[q] = make_float4(0.f, 0.f, 0.f, 0.f);
}

// ---------------------------------------------------------------------------
// 128-bit reduction (fire-and-forget) — sm_90+ vector atomic
// ---------------------------------------------------------------------------
__device__ __forceinline__ void red_add_v4(float4* p, float4 s) {
    asm volatile("red.global.add.v4.f32 [%0], {%1, %2, %3, %4};"
                 :: "l"(p), "f"(s.x), "f"(s.y), "f"(s.z), "f"(s.w)
                 : "memory");
}

// flush: pre-divide partial run sum by the segment's inv, REDG into out.
__device__ __forceinline__ void flush_seg(float4* __restrict__ out4,
                                          int seg, float4 s, int sub) {
    float inv = __ldg(g_inv + seg);     // 8 lanes same addr -> broadcast
    red_add_v4(&out4[(long long)seg * 8 + sub],
               make_float4(s.x * inv, s.y * inv, s.z * inv, s.w * inv));
}

// ---------------------------------------------------------------------------
// Kernel 2: gather + sorted-segment mean (round-3 engine).
// Warp = 4 groups of 8 lanes; group g owns contiguous edges
// [start + g*32, start + g*32 + 32). Lane sub owns feature columns
// [sub*4, sub*4+4) as a float4. Phase 1 issues 8 independent LDG.128 row
// reads (MLP=8/lane); phase 2 run-length accumulates, flushing pre-divided
// partials with one REDG.128 per lane on segment change.
// ---------------------------------------------------------------------------
__global__ void __launch_bounds__(256)
k_agg(const float* __restrict__ src,
      const int*   __restrict__ gidx,
      const int*   __restrict__ sid,
      float4*      __restrict__ out4,
      int E)
{
    const int lane = threadIdx.x & 31;
    const int sub  = lane & 7;
    const long long warp  = ((long long)blockIdx.x * blockDim.x + threadIdx.x) >> 5;
    const long long start = warp * (long long)EPW;
    if (start >= E) return;

    if (start + EPW <= E) {
        // ---------- fast path: full 128-edge chunk ----------
        int4 gi4 = __ldg((const int4*)(gidx + start) + lane);
        int4 si4 = __ldg((const int4*)(sid  + start) + lane);
        int gi[4] = {gi4.x, gi4.y, gi4.z, gi4.w};
        int si[4] = {si4.x, si4.y, si4.z, si4.w};

        int    cur = -1;
        float4 sum = make_float4(0.f, 0.f, 0.f, 0.f);
        int    cnt = 0;

        #pragma unroll
        for (int jo = 0; jo < 32; jo += 8) {
            float4 val[8];
            #pragma unroll
            for (int jj = 0; jj < 8; ++jj) {
                const int j = jo + jj;
                int idx = __shfl_sync(FULL_MASK, gi[j & 3], j >> 2, 8);
                val[jj] = __ldg((const float4*)(src + (long long)idx * D) + sub);
            }
            #pragma unroll
            for (int jj = 0; jj < 8; ++jj) {
                const int j = jo + jj;
                int seg = __shfl_sync(FULL_MASK, si[j & 3], j >> 2, 8);
                if (seg != cur) {
                    if (cnt) flush_seg(out4, cur, sum, sub);
                    cur = seg; sum = make_float4(0.f, 0.f, 0.f, 0.f); cnt = 0;
                }
                sum.x += val[jj].x; sum.y += val[jj].y;
                sum.z += val[jj].z; sum.w += val[jj].w;
                ++cnt;
            }
        }
        if (cnt) flush_seg(out4, cur, sum, sub);
    } else {
        // ---------- tail path: partial chunk, per-group scalar loop ----------
        const int group = lane >> 3;
        long long gstart = start + (long long)group * 32;
        long long gend   = min(gstart + 32, (long long)E);

        int    cur = -1;
        float4 sum = make_float4(0.f, 0.f, 0.f, 0.f);
        int    cnt = 0;

        for (long long e = gstart; e < gend; ++e) {
            int idx = __ldg(gidx + e);
            int seg = __ldg(sid  + e);
            float4 v = __ldg((const float4*)(src + (long long)idx * D) + sub);
            if (seg != cur) {
                if (cnt) flush_seg(out4, cur, sum, sub);
                cur = seg; sum = make_float4(0.f, 0.f, 0.f, 0.f); cnt = 0;
            }
            sum.x += v.x; sum.y += v.y; sum.z += v.z; sum.w += v.w;
            ++cnt;
        }
        if (cnt) flush_seg(out4, cur, sum, sub);
    }
}

// ---------------------------------------------------------------------------
extern "C" void kernel_launch(void* const* d_in, const int* in_sizes, int n_in,
                              void* d_out, int out_size)
{
    const float* src  = (const float*)d_in[0];   // [N, 32] f32
    const int*   gidx = (const int*)  d_in[1];   // [E] i32
    const int*   sid  = (const int*)  d_in[2];   // [E] i32 (sorted)
    float4*      out4 = (float4*)d_out;          // [N, 32] f32

    const int E = in_sizes[1];
    const int N = out_size / D;

    // 1) counts -> g_inv, zero output
    {
        int blocks = (N + SPB - 1) / SPB;
        k_pre<<<blocks, SPB>>>(sid, out4, E, N);
    }
    // 2) gather + pre-divided segment sum into out
    {
        long long warps  = ((long long)E + EPW - 1) / EPW;
        long long tcount = warps * 32;
        int threads = 256;
        int blocks  = (int)((tcount + threads - 1) / threads);
        k_agg<<<blocks, threads>>>(src, gidx, sid, out4, E);
    }
}